// round 16
// baseline (speedup 1.0000x reference)
#include <cuda_runtime.h>
#include <cuda_fp16.h>
#include <cstdint>

#define Bb 8
#define Nn 4096
#define Ff 240
#define Hh 32
#define Ll 240
#define NC (Bb * Hh)   // 256 folded columns
#define KSPLIT 2
#define KCHUNK (Nn / KSPLIT)      // 2048

// Scratch (allocation-free rule: __device__ globals)
__device__ __half g_Ht[NC * Nn];            // H transposed [c][k], fp16, 2 MB
__device__ __half g_W2t[Ll * Hh];           // W2 transposed [l][h], fp16
__device__ float  g_P[KSPLIT * Nn * NC];    // split-K partials [kz][c][m], 8 MB

// ===========================================================================
__device__ __forceinline__ void cpasync16(void* dst, const void* src) {
    uint32_t d = (uint32_t)__cvta_generic_to_shared(dst);
    asm volatile("cp.async.cg.shared.global [%0], [%1], 16;\n" :: "r"(d), "l"(src));
}
__device__ __forceinline__ void mma_f16(float c[4], const uint32_t a[4],
                                        const uint32_t b[2]) {
    asm volatile(
        "mma.sync.aligned.m16n8k16.row.col.f32.f16.f16.f32 "
        "{%0,%1,%2,%3}, {%4,%5,%6,%7}, {%8,%9}, {%0,%1,%2,%3};"
        : "+f"(c[0]), "+f"(c[1]), "+f"(c[2]), "+f"(c[3])
        : "r"(a[0]), "r"(a[1]), "r"(a[2]), "r"(a[3]), "r"(b[0]), "r"(b[1]));
}

// ===========================================================================
// K1: blocks [0,512) compute g_Ht = fp16(x @ W1); block 512 converts W2t.
// CTA = 64 n-rows x 1 batch, 256 thr (8 warps, m16 x n16 warp tiles).
// ===========================================================================
#define ASTRH 264
#define K1_A_H (64 * ASTRH)
#define K1_W_H (Hh * ASTRH)
#define DSTRH 72
#define K1_SMEM ((K1_A_H + K1_W_H) * 2)   // 50688 B

__global__ __launch_bounds__(256) void k1_xw1(const float* __restrict__ W2,
                                              const float* __restrict__ x,
                                              const float* __restrict__ W1) {
    const int bid = blockIdx.x;
    const int tid = threadIdx.x;

    if (bid == 512) {   // W2t conversion
        for (int i = tid; i < Ll * Hh; i += 256) {
            int l = i >> 5, h = i & 31;
            g_W2t[i] = __float2half_rn(W2[h * Ll + l]);
        }
        return;
    }

    extern __shared__ __half sm1h[];
    __half* As = sm1h;              // [64][ASTRH]
    __half* Ws = sm1h + K1_A_H;     // [32][ASTRH]

    const int warp = tid >> 5;
    const int lane = tid & 31;
    const int b  = bid >> 6;
    const int n0 = (bid & 63) * 64;

    const float* xbase = x + ((size_t)b * Nn + n0) * Ff;
    #pragma unroll
    for (int t = 0; t < 15; t++) {
        int c = tid + t * 256;
        int row = c / 60, f4 = c % 60;
        float4 v = *reinterpret_cast<const float4*>(
            xbase + (size_t)row * Ff + f4 * 4);
        __half2 h0 = __floats2half2_rn(v.x, v.y);
        __half2 h1 = __floats2half2_rn(v.z, v.w);
        uint2 u;
        u.x = *reinterpret_cast<uint32_t*>(&h0);
        u.y = *reinterpret_cast<uint32_t*>(&h1);
        *reinterpret_cast<uint2*>(&As[row * ASTRH + f4 * 4]) = u;
    }
    for (int i = tid; i < Ff * Hh; i += 256) {
        int f = i >> 5, h = i & 31;
        Ws[h * ASTRH + f] = __float2half_rn(W1[i]);
    }
    __syncthreads();

    const int wm  = (warp >> 1) * 16;
    const int wnh = (warp & 1) * 16;
    const int r  = lane >> 2;
    const int cc = lane & 3;

    float acc[2][4];
    #pragma unroll
    for (int ni = 0; ni < 2; ni++)
        #pragma unroll
        for (int q = 0; q < 4; q++) acc[ni][q] = 0.f;

    #pragma unroll
    for (int ks = 0; ks < 15; ks++) {
        const int k0 = ks * 16;
        uint32_t af[4];
        const __half* ap = As + (wm + r) * ASTRH + k0 + 2 * cc;
        af[0] = *reinterpret_cast<const uint32_t*>(ap);
        af[1] = *reinterpret_cast<const uint32_t*>(ap + 8 * ASTRH);
        af[2] = *reinterpret_cast<const uint32_t*>(ap + 8);
        af[3] = *reinterpret_cast<const uint32_t*>(ap + 8 * ASTRH + 8);
        #pragma unroll
        for (int ni = 0; ni < 2; ni++) {
            uint32_t bf[2];
            const __half* bp = Ws + (wnh + ni * 8 + r) * ASTRH + k0 + 2 * cc;
            bf[0] = *reinterpret_cast<const uint32_t*>(bp);
            bf[1] = *reinterpret_cast<const uint32_t*>(bp + 8);
            mma_f16(acc[ni], af, bf);
        }
    }

    __syncthreads();
    __half* Ds = As;
    #pragma unroll
    for (int ni = 0; ni < 2; ni++) {
        int h = wnh + ni * 8 + 2 * cc;
        Ds[(h    ) * DSTRH + wm + r    ] = __float2half_rn(acc[ni][0]);
        Ds[(h + 1) * DSTRH + wm + r    ] = __float2half_rn(acc[ni][1]);
        Ds[(h    ) * DSTRH + wm + r + 8] = __float2half_rn(acc[ni][2]);
        Ds[(h + 1) * DSTRH + wm + r + 8] = __float2half_rn(acc[ni][3]);
    }
    __syncthreads();

    {
        int h = tid >> 3, g = tid & 7;
        uint4 v = *reinterpret_cast<const uint4*>(Ds + h * DSTRH + g * 8);
        *reinterpret_cast<uint4*>(
            &g_Ht[(size_t)(b * Hh + h) * Nn + n0 + g * 8]) = v;
    }
}

// ===========================================================================
// K2: split-K fp16 GEMM; A read DIRECTLY from fp32 `a` (reg prefetch -> cvt.rn
// -> STS fp16, double-buffered), B cp.async fp16 from g_Ht (4-stage ring).
// BM=128, BN=64, BK=32; 256 thr, 8 warps (4m x 2n), warp tile 32x32.
// grid (32, 4, 2) = 256 CTAs = 2/SM.
// ===========================================================================
#define K2_BM 128
#define K2_BN 64
#define K2_BK 32
#define K2_NIT (KCHUNK / K2_BK)    // 64
#define HSTR 40
#define A_ST_B (K2_BM * HSTR * 2)  // 10240 (one A buffer)
#define B_ST_B (K2_BN * HSTR * 2)  // 5120  (one B stage)
#define BSTAGES 4
#define K2_SMEM (2 * A_ST_B + BSTAGES * B_ST_B)   // 40960 B

__global__ __launch_bounds__(256) void k2_tc(const float* __restrict__ A) {
    extern __shared__ char smem[];
    char* Abuf = smem;                         // [2][A_ST_B]
    char* Bbuf = smem + 2 * A_ST_B;            // [4][B_ST_B]

    const int tid  = threadIdx.x;
    const int warp = tid >> 5;
    const int lane = tid & 31;
    const int bm   = blockIdx.x * K2_BM;
    const int bnoff = blockIdx.y * K2_BN;
    const int kbase = blockIdx.z * KCHUNK;

    const int wm = (warp & 3) * 32;
    const int wn = (warp >> 2) * 32;
    const int r  = lane >> 2;
    const int cc = lane & 3;

    // A mapping: 1024 16B-fp32 chunks (128 rows x 8) / 256 thr = 4 each
    const int a_row = tid >> 1;          // 0..127 (rows, pairs: +0/+... )
    const int a_q   = tid & 1;           // chunk pair base
    // each thread: rows a_row with chunks {a_q*4 .. a_q*4+3}? Better: 4 chunks
    // spread: c = tid + t*256, row = c>>3, q = c&7  (coalesced 128B rows)

    auto ldgA = [&](int it, float4 pr[4]) {
        int kcol = kbase + it * K2_BK;
        #pragma unroll
        for (int t = 0; t < 4; t++) {
            int c = tid + t * 256;
            int row = c >> 3, q = c & 7;
            pr[t] = *reinterpret_cast<const float4*>(
                A + (size_t)(bm + row) * Nn + kcol + q * 4);
        }
    };
    auto stsA = [&](int buf, const float4 pr[4]) {
        __half* ab = reinterpret_cast<__half*>(Abuf + buf * A_ST_B);
        #pragma unroll
        for (int t = 0; t < 4; t++) {
            int c = tid + t * 256;
            int row = c >> 3, q = c & 7;
            __half2 h0 = __floats2half2_rn(pr[t].x, pr[t].y);
            __half2 h1 = __floats2half2_rn(pr[t].z, pr[t].w);
            uint2 u;
            u.x = *reinterpret_cast<uint32_t*>(&h0);
            u.y = *reinterpret_cast<uint32_t*>(&h1);
            *reinterpret_cast<uint2*>(&ab[row * HSTR + q * 4]) = u;
        }
    };
    auto loadB = [&](int it) {
        char* bb = Bbuf + (it % BSTAGES) * B_ST_B;
        int kcol = kbase + it * K2_BK;
        int row = tid >> 2, q = tid & 3;     // 256 chunks
        cpasync16(bb + row * (HSTR * 2) + q * 16,
                  g_Ht + (size_t)(bnoff + row) * Nn + kcol + q * 8);
    };

    float acc[2][4][4];
    #pragma unroll
    for (int mi = 0; mi < 2; mi++)
        #pragma unroll
        for (int ni = 0; ni < 4; ni++)
            #pragma unroll
            for (int q = 0; q < 4; q++) acc[mi][ni][q] = 0.f;

    // prologue
    float4 preg[2][4];
    ldgA(0, preg[0]);
    ldgA(1, preg[1]);
    loadB(0); asm volatile("cp.async.commit_group;\n");
    loadB(1); asm volatile("cp.async.commit_group;\n");
    loadB(2); asm volatile("cp.async.commit_group;\n");
    stsA(0, preg[0]);

    for (int i = 0; i < K2_NIT; i++) {
        asm volatile("cp.async.wait_group 2;\n");
        __syncthreads();   // A(i) STS'd + B(i) landed

        if (i + 3 < K2_NIT) loadB(i + 3);
        asm volatile("cp.async.commit_group;\n");
        if (i + 1 < K2_NIT) stsA((i + 1) & 1, preg[(i + 1) & 1]);
        if (i + 2 < K2_NIT) ldgA(i + 2, preg[i & 1]);

        const __half* as = reinterpret_cast<const __half*>(
            Abuf + (i & 1) * A_ST_B);
        const __half* bs = reinterpret_cast<const __half*>(
            Bbuf + (i % BSTAGES) * B_ST_B);

        #pragma unroll
        for (int ks = 0; ks < 2; ks++) {
            const int k0 = ks * 16;
            uint32_t af[2][4];
            #pragma unroll
            for (int mi = 0; mi < 2; mi++) {
                const __half* ap = as + (wm + mi * 16 + r) * HSTR + k0 + 2 * cc;
                af[mi][0] = *reinterpret_cast<const uint32_t*>(ap);
                af[mi][1] = *reinterpret_cast<const uint32_t*>(ap + 8 * HSTR);
                af[mi][2] = *reinterpret_cast<const uint32_t*>(ap + 8);
                af[mi][3] = *reinterpret_cast<const uint32_t*>(ap + 8 * HSTR + 8);
            }
            uint32_t bf[4][2];
            #pragma unroll
            for (int ni = 0; ni < 4; ni++) {
                const __half* bp = bs + (wn + ni * 8 + r) * HSTR + k0 + 2 * cc;
                bf[ni][0] = *reinterpret_cast<const uint32_t*>(bp);
                bf[ni][1] = *reinterpret_cast<const uint32_t*>(bp + 8);
            }
            #pragma unroll
            for (int mi = 0; mi < 2; mi++)
                #pragma unroll
                for (int ni = 0; ni < 4; ni++)
                    mma_f16(acc[mi][ni], af[mi], bf[ni]);
        }
    }

    float* P = g_P + (size_t)blockIdx.z * Nn * NC;
    #pragma unroll
    for (int mi = 0; mi < 2; mi++) {
        #pragma unroll
        for (int ni = 0; ni < 4; ni++) {
            int gm = bm + wm + mi * 16 + r;
            int gc = bnoff + wn + ni * 8 + cc * 2;
            P[(size_t)gc * Nn + gm]           = acc[mi][ni][0];
            P[(size_t)(gc + 1) * Nn + gm]     = acc[mi][ni][1];
            P[(size_t)gc * Nn + gm + 8]       = acc[mi][ni][2];
            P[(size_t)(gc + 1) * Nn + gm + 8] = acc[mi][ni][3];
        }
    }
}

// ===========================================================================
// K3 (fp16 mma): out[b,n,l] = relu(P0+P1+b1) @ W2 + b2
// CTA: 32 n-rows x 1 batch; 128 thr, 4 warps (2m x 2l); grid (128, 8) = 1024.
// ===========================================================================
__global__ __launch_bounds__(128) void k3_out(const float* __restrict__ b1,
                                              const float* __restrict__ b2,
                                              float* __restrict__ out) {
    __shared__ __half Rs[32 * HSTR];
    __shared__ __half Ws[Ll * HSTR];

    const int tid  = threadIdx.x;
    const int warp = tid >> 5;
    const int lane = tid & 31;
    const int b  = blockIdx.y;
    const int n0 = blockIdx.x * 32;

    for (int c = tid; c < Ll * 4; c += 128) {
        int l = c >> 2, q = c & 3;
        cpasync16(Ws + l * HSTR + q * 8, g_W2t + l * Hh + q * 8);
    }
    asm volatile("cp.async.commit_group;\n");

    {
        int h  = tid >> 2;
        int nq = tid & 3;
        size_t idx = (size_t)(b * Hh + h) * Nn + n0 + nq * 8;
        float4 p0a = *reinterpret_cast<const float4*>(&g_P[idx]);
        float4 p0b = *reinterpret_cast<const float4*>(&g_P[idx + 4]);
        float4 p1a = *reinterpret_cast<const float4*>(&g_P[idx + (size_t)Nn * NC]);
        float4 p1b = *reinterpret_cast<const float4*>(&g_P[idx + (size_t)Nn * NC + 4]);
        float bv = __ldg(&b1[h]);
        float v[8] = {p0a.x + p1a.x + bv, p0a.y + p1a.y + bv,
                      p0a.z + p1a.z + bv, p0a.w + p1a.w + bv,
                      p0b.x + p1b.x + bv, p0b.y + p1b.y + bv,
                      p0b.z + p1b.z + bv, p0b.w + p1b.w + bv};
        #pragma unroll
        for (int j = 0; j < 8; j++)
            Rs[(nq * 8 + j) * HSTR + h] = __float2half_rn(fmaxf(v[j], 0.f));
    }
    asm volatile("cp.async.wait_group 0;\n");
    __syncthreads();

    const int wm  = (warp >> 1) * 16;
    const int wnl = (warp & 1) * 120;
    const int r   = lane >> 2;
    const int cc  = lane & 3;

    float acc[15][4];
    #pragma unroll
    for (int ni = 0; ni < 15; ni++)
        #pragma unroll
        for (int q = 0; q < 4; q++) acc[ni][q] = 0.f;

    #pragma unroll
    for (int ks = 0; ks < 2; ks++) {
        const int k0 = ks * 16;
        uint32_t af[4];
        const __half* ap = Rs + (wm + r) * HSTR + k0 + 2 * cc;
        af[0] = *reinterpret_cast<const uint32_t*>(ap);
        af[1] = *reinterpret_cast<const uint32_t*>(ap + 8 * HSTR);
        af[2] = *reinterpret_cast<const uint32_t*>(ap + 8);
        af[3] = *reinterpret_cast<const uint32_t*>(ap + 8 * HSTR + 8);
        #pragma unroll
        for (int ni = 0; ni < 15; ni++) {
            uint32_t bf[2];
            const __half* bp = Ws + (wnl + ni * 8 + r) * HSTR + k0 + 2 * cc;
            bf[0] = *reinterpret_cast<const uint32_t*>(bp);
            bf[1] = *reinterpret_cast<const uint32_t*>(bp + 8);
            mma_f16(acc[ni], af, bf);
        }
    }

    #pragma unroll
    for (int ni = 0; ni < 15; ni++) {
        int l = wnl + ni * 8 + 2 * cc;
        float bv0 = __ldg(&b2[l]), bv1 = __ldg(&b2[l + 1]);
        size_t row0 = (size_t)b * Nn + n0 + wm + r;
        float2 v0 = make_float2(acc[ni][0] + bv0, acc[ni][1] + bv1);
        float2 v1 = make_float2(acc[ni][2] + bv0, acc[ni][3] + bv1);
        *reinterpret_cast<float2*>(&out[row0 * Ll + l])       = v0;
        *reinterpret_cast<float2*>(&out[(row0 + 8) * Ll + l]) = v1;
    }
}

// ===========================================================================
extern "C" void kernel_launch(void* const* d_in, const int* in_sizes, int n_in,
                              void* d_out, int out_size) {
    const float* x  = (const float*)d_in[0];
    const float* a  = (const float*)d_in[1];
    const float* W1 = (const float*)d_in[2];
    const float* b1 = (const float*)d_in[3];
    const float* W2 = (const float*)d_in[4];
    const float* b2 = (const float*)d_in[5];
    float* out = (float*)d_out;

    cudaFuncSetAttribute(k1_xw1, cudaFuncAttributeMaxDynamicSharedMemorySize,
                         K1_SMEM);
    k1_xw1<<<513, 256, K1_SMEM>>>(W2, x, W1);

    cudaFuncSetAttribute(k2_tc, cudaFuncAttributeMaxDynamicSharedMemorySize,
                         K2_SMEM);
    dim3 g2(Nn / K2_BM, NC / K2_BN, KSPLIT);
    k2_tc<<<g2, 256, K2_SMEM>>>(a);

    dim3 g3(Nn / 32, Bb);
    k3_out<<<g3, 128>>>(b1, b2, out);
}

// round 17
// speedup vs baseline: 1.6392x; 1.6392x over previous
#include <cuda_runtime.h>
#include <cuda_fp16.h>
#include <cstdint>

#define Bb 8
#define Nn 4096
#define Ff 240
#define Hh 32
#define Ll 240
#define NC (Bb * Hh)   // 256 folded columns
#define KSPLIT 4
#define KCHUNK (Nn / KSPLIT)      // 1024

// Scratch (allocation-free rule: __device__ globals)
__device__ __half g_a16[(size_t)Nn * Nn];   // fp16 copy of a, 32 MB
__device__ __half g_Ht[NC * Nn];            // H transposed [c][k], fp16, 2 MB
__device__ __half g_W2t[Ll * Hh];           // W2 transposed [l][h], fp16
__device__ float  g_P[KSPLIT * Nn * NC];    // split-K partials [kz][c][m], 16 MB

// ===========================================================================
__device__ __forceinline__ void cpasync16(void* dst, const void* src) {
    uint32_t d = (uint32_t)__cvta_generic_to_shared(dst);
    asm volatile("cp.async.cg.shared.global [%0], [%1], 16;\n" :: "r"(d), "l"(src));
}
__device__ __forceinline__ void mma_f16(float c[4], const uint32_t a[4],
                                        const uint32_t b[2]) {
    asm volatile(
        "mma.sync.aligned.m16n8k16.row.col.f32.f16.f16.f32 "
        "{%0,%1,%2,%3}, {%4,%5,%6,%7}, {%8,%9}, {%0,%1,%2,%3};"
        : "+f"(c[0]), "+f"(c[1]), "+f"(c[2]), "+f"(c[3])
        : "r"(a[0]), "r"(a[1]), "r"(a[2]), "r"(a[3]), "r"(b[0]), "r"(b[1]));
}

// ===========================================================================
// K01: fused launch (256 thr/block).
//   blocks [0, 1024)  : k1 — g_Ht[b*32+h][n] = fp16(x @ W1), 32-row tiles
//   block 1024        : W2t conversion
//   blocks (1024, ...]: g_a16 = (half)a streaming conversion (8192 blocks)
// Small smem (33.8 KB) -> 6 CTAs/SM so conversion blocks keep DRAM busy.
// ===========================================================================
#define ASTRH 264   // halves per As/Ws row (132 words, 132%32=4: conflict-free)
#define K1_A_H (32 * ASTRH)
#define K1_W_H (Hh * ASTRH)
#define DSTRH 40
#define K01_SMEM ((K1_A_H + K1_W_H) * 2)   // 33792 B

__global__ __launch_bounds__(256) void k01(const float* __restrict__ a,
                                           const float* __restrict__ W2,
                                           const float* __restrict__ x,
                                           const float* __restrict__ W1) {
    const int bid = blockIdx.x;
    const int tid = threadIdx.x;

    if (bid == 1024) {   // W2t conversion
        for (int i = tid; i < Ll * Hh; i += 256) {
            int l = i >> 5, h = i & 31;
            g_W2t[i] = __float2half_rn(W2[h * Ll + l]);
        }
        return;
    }
    if (bid > 1024) {    // a conversion: 8192 stream blocks
        size_t i = ((size_t)(bid - 1025) * 256 + tid) * 8;
        float4 v0 = *reinterpret_cast<const float4*>(a + i);
        float4 v1 = *reinterpret_cast<const float4*>(a + i + 4);
        __half2 h[4];
        h[0] = __floats2half2_rn(v0.x, v0.y);
        h[1] = __floats2half2_rn(v0.z, v0.w);
        h[2] = __floats2half2_rn(v1.x, v1.y);
        h[3] = __floats2half2_rn(v1.z, v1.w);
        *reinterpret_cast<uint4*>(&g_a16[i]) = *reinterpret_cast<uint4*>(h);
        return;
    }

    // ---- k1 body: CTA = 32 n-rows x 1 batch; 8 warps, warp tile m16 x n8
    extern __shared__ __half sm1h[];
    __half* As = sm1h;              // [32][ASTRH]
    __half* Ws = sm1h + K1_A_H;     // [32][ASTRH]  W1t [h][f]

    const int warp = tid >> 5;
    const int lane = tid & 31;
    const int b  = bid >> 7;
    const int n0 = (bid & 127) * 32;

    // convert x tile (32 x 240 fp32 -> fp16): 1920 16B-chunks
    const float* xbase = x + ((size_t)b * Nn + n0) * Ff;
    #pragma unroll
    for (int t = 0; t < 8; t++) {
        int c = tid + t * 256;
        if (c < 1920) {
            int row = c / 60, f4 = c % 60;
            float4 v = *reinterpret_cast<const float4*>(
                xbase + (size_t)row * Ff + f4 * 4);
            __half2 h0 = __floats2half2_rn(v.x, v.y);
            __half2 h1 = __floats2half2_rn(v.z, v.w);
            uint2 u;
            u.x = *reinterpret_cast<uint32_t*>(&h0);
            u.y = *reinterpret_cast<uint32_t*>(&h1);
            *reinterpret_cast<uint2*>(&As[row * ASTRH + f4 * 4]) = u;
        }
    }
    // W1t: vectorized transpose load (1920 float4 chunks)
    #pragma unroll
    for (int t = 0; t < 8; t++) {
        int c = tid + t * 256;
        if (c < 1920) {
            int f = c >> 3, h4 = c & 7;
            float4 v = *reinterpret_cast<const float4*>(W1 + f * Hh + h4 * 4);
            Ws[(h4 * 4 + 0) * ASTRH + f] = __float2half_rn(v.x);
            Ws[(h4 * 4 + 1) * ASTRH + f] = __float2half_rn(v.y);
            Ws[(h4 * 4 + 2) * ASTRH + f] = __float2half_rn(v.z);
            Ws[(h4 * 4 + 3) * ASTRH + f] = __float2half_rn(v.w);
        }
    }
    __syncthreads();

    const int wm = (warp & 1) * 16;      // 2 m-tiles
    const int wh = (warp >> 1) * 8;      // 4 h-tiles of 8
    const int r  = lane >> 2;
    const int cc = lane & 3;

    float acc[4] = {0.f, 0.f, 0.f, 0.f};

    #pragma unroll
    for (int ks = 0; ks < 15; ks++) {
        const int k0 = ks * 16;
        uint32_t af[4];
        const __half* ap = As + (wm + r) * ASTRH + k0 + 2 * cc;
        af[0] = *reinterpret_cast<const uint32_t*>(ap);
        af[1] = *reinterpret_cast<const uint32_t*>(ap + 8 * ASTRH);
        af[2] = *reinterpret_cast<const uint32_t*>(ap + 8);
        af[3] = *reinterpret_cast<const uint32_t*>(ap + 8 * ASTRH + 8);
        uint32_t bf[2];
        const __half* bp = Ws + (wh + r) * ASTRH + k0 + 2 * cc;
        bf[0] = *reinterpret_cast<const uint32_t*>(bp);
        bf[1] = *reinterpret_cast<const uint32_t*>(bp + 8);
        mma_f16(acc, af, bf);
    }

    __syncthreads();
    __half* Ds = As;                     // [32 h][DSTRH] overlay
    {
        int h = wh + 2 * cc;
        Ds[(h    ) * DSTRH + wm + r    ] = __float2half_rn(acc[0]);
        Ds[(h + 1) * DSTRH + wm + r    ] = __float2half_rn(acc[1]);
        Ds[(h    ) * DSTRH + wm + r + 8] = __float2half_rn(acc[2]);
        Ds[(h + 1) * DSTRH + wm + r + 8] = __float2half_rn(acc[3]);
    }
    __syncthreads();

    if (tid < 128) {   // 32 h x 4 uint4-chunks
        int h = tid >> 2, g = tid & 3;
        uint4 v = *reinterpret_cast<const uint4*>(Ds + h * DSTRH + g * 8);
        *reinterpret_cast<uint4*>(
            &g_Ht[(size_t)(b * Hh + h) * Nn + n0 + g * 8]) = v;
    }
}

// ===========================================================================
// K2: pure-fp16 split-K mma.sync GEMM (R9-proven shape + KSPLIT=4 -> 2/SM).
// BM=128, BN=128, BK=32; 512 thr, 16 warps (4m x 4n), warp tile 32x32.
// 4-stage cp.async ring. grid (32, 2, 4) = 256 CTAs.
// ===========================================================================
#define K2_BM 128
#define K2_BN 128
#define K2_BK 32
#define K2_NIT (KCHUNK / K2_BK)    // 32
#define HSTR 40
#define A_ST_B (K2_BM * HSTR * 2)
#define B_ST_B (K2_BN * HSTR * 2)
#define STAGE_B (A_ST_B + B_ST_B)
#define STAGES 4
#define K2_SMEM (STAGES * STAGE_B) // 81920 B

__global__ __launch_bounds__(512) void k2_tc() {
    extern __shared__ char smem[];

    const int tid  = threadIdx.x;
    const int warp = tid >> 5;
    const int lane = tid & 31;
    const int bm   = blockIdx.x * K2_BM;
    const int bnoff = blockIdx.y * K2_BN;
    const int kbase = blockIdx.z * KCHUNK;

    const int wm = (warp & 3) * 32;
    const int wn = (warp >> 2) * 32;
    const int r  = lane >> 2;
    const int cc = lane & 3;

    const int ld_row = tid >> 2;
    const int ld_q   = tid & 3;

    auto load_tile = [&](int it) {
        char* ab = smem + (it % STAGES) * STAGE_B;
        char* bb = ab + A_ST_B;
        int kcol = kbase + it * K2_BK;
        cpasync16(ab + ld_row * (HSTR * 2) + ld_q * 16,
                  g_a16 + (size_t)(bm + ld_row) * Nn + kcol + ld_q * 8);
        cpasync16(bb + ld_row * (HSTR * 2) + ld_q * 16,
                  g_Ht + (size_t)(bnoff + ld_row) * Nn + kcol + ld_q * 8);
    };

    float acc[2][4][4];
    #pragma unroll
    for (int mi = 0; mi < 2; mi++)
        #pragma unroll
        for (int ni = 0; ni < 4; ni++)
            #pragma unroll
            for (int q = 0; q < 4; q++) acc[mi][ni][q] = 0.f;

    load_tile(0); asm volatile("cp.async.commit_group;\n");
    load_tile(1); asm volatile("cp.async.commit_group;\n");
    load_tile(2); asm volatile("cp.async.commit_group;\n");

    for (int i = 0; i < K2_NIT; i++) {
        asm volatile("cp.async.wait_group 2;\n");
        __syncthreads();
        if (i + 3 < K2_NIT) load_tile(i + 3);
        asm volatile("cp.async.commit_group;\n");

        const __half* as = reinterpret_cast<const __half*>(
            smem + (i % STAGES) * STAGE_B);
        const __half* bs = reinterpret_cast<const __half*>(
            smem + (i % STAGES) * STAGE_B + A_ST_B);

        #pragma unroll
        for (int ks = 0; ks < 2; ks++) {
            const int k0 = ks * 16;
            uint32_t af[2][4];
            #pragma unroll
            for (int mi = 0; mi < 2; mi++) {
                const __half* ap = as + (wm + mi * 16 + r) * HSTR + k0 + 2 * cc;
                af[mi][0] = *reinterpret_cast<const uint32_t*>(ap);
                af[mi][1] = *reinterpret_cast<const uint32_t*>(ap + 8 * HSTR);
                af[mi][2] = *reinterpret_cast<const uint32_t*>(ap + 8);
                af[mi][3] = *reinterpret_cast<const uint32_t*>(ap + 8 * HSTR + 8);
            }
            uint32_t bf[4][2];
            #pragma unroll
            for (int ni = 0; ni < 4; ni++) {
                const __half* bp = bs + (wn + ni * 8 + r) * HSTR + k0 + 2 * cc;
                bf[ni][0] = *reinterpret_cast<const uint32_t*>(bp);
                bf[ni][1] = *reinterpret_cast<const uint32_t*>(bp + 8);
            }
            #pragma unroll
            for (int mi = 0; mi < 2; mi++)
                #pragma unroll
                for (int ni = 0; ni < 4; ni++)
                    mma_f16(acc[mi][ni], af[mi], bf[ni]);
        }
    }

    float* P = g_P + (size_t)blockIdx.z * Nn * NC;
    #pragma unroll
    for (int mi = 0; mi < 2; mi++) {
        #pragma unroll
        for (int ni = 0; ni < 4; ni++) {
            int gm = bm + wm + mi * 16 + r;
            int gc = bnoff + wn + ni * 8 + cc * 2;
            P[(size_t)gc * Nn + gm]           = acc[mi][ni][0];
            P[(size_t)(gc + 1) * Nn + gm]     = acc[mi][ni][1];
            P[(size_t)gc * Nn + gm + 8]       = acc[mi][ni][2];
            P[(size_t)(gc + 1) * Nn + gm + 8] = acc[mi][ni][3];
        }
    }
}

// ===========================================================================
// K3 (fp16 mma): out[b,n,l] = relu(P0+P1+P2+P3+b1) @ W2 + b2
// CTA: 32 n-rows x 1 batch; 128 thr, 4 warps (2m x 2l); grid (128, 8) = 1024.
// ===========================================================================
__global__ __launch_bounds__(128) void k3_out(const float* __restrict__ b1,
                                              const float* __restrict__ b2,
                                              float* __restrict__ out) {
    __shared__ __half Rs[32 * HSTR];
    __shared__ __half Ws[Ll * HSTR];

    const int tid  = threadIdx.x;
    const int warp = tid >> 5;
    const int lane = tid & 31;
    const int b  = blockIdx.y;
    const int n0 = blockIdx.x * 32;

    for (int c = tid; c < Ll * 4; c += 128) {
        int l = c >> 2, q = c & 3;
        cpasync16(Ws + l * HSTR + q * 8, g_W2t + l * Hh + q * 8);
    }
    asm volatile("cp.async.commit_group;\n");

    {
        int h  = tid >> 2;
        int nq = tid & 3;
        size_t idx = (size_t)(b * Hh + h) * Nn + n0 + nq * 8;
        const size_t PS = (size_t)Nn * NC;
        float v[8];
        #pragma unroll
        for (int half4 = 0; half4 < 2; half4++) {
            float4 s0 = *reinterpret_cast<const float4*>(&g_P[idx + half4 * 4]);
            float4 s1 = *reinterpret_cast<const float4*>(&g_P[idx + PS + half4 * 4]);
            float4 s2 = *reinterpret_cast<const float4*>(&g_P[idx + 2 * PS + half4 * 4]);
            float4 s3 = *reinterpret_cast<const float4*>(&g_P[idx + 3 * PS + half4 * 4]);
            v[half4 * 4 + 0] = s0.x + s1.x + s2.x + s3.x;
            v[half4 * 4 + 1] = s0.y + s1.y + s2.y + s3.y;
            v[half4 * 4 + 2] = s0.z + s1.z + s2.z + s3.z;
            v[half4 * 4 + 3] = s0.w + s1.w + s2.w + s3.w;
        }
        float bv = __ldg(&b1[h]);
        #pragma unroll
        for (int j = 0; j < 8; j++)
            Rs[(nq * 8 + j) * HSTR + h] = __float2half_rn(fmaxf(v[j] + bv, 0.f));
    }
    asm volatile("cp.async.wait_group 0;\n");
    __syncthreads();

    const int wm  = (warp >> 1) * 16;
    const int wnl = (warp & 1) * 120;
    const int r   = lane >> 2;
    const int cc  = lane & 3;

    float acc[15][4];
    #pragma unroll
    for (int ni = 0; ni < 15; ni++)
        #pragma unroll
        for (int q = 0; q < 4; q++) acc[ni][q] = 0.f;

    #pragma unroll
    for (int ks = 0; ks < 2; ks++) {
        const int k0 = ks * 16;
        uint32_t af[4];
        const __half* ap = Rs + (wm + r) * HSTR + k0 + 2 * cc;
        af[0] = *reinterpret_cast<const uint32_t*>(ap);
        af[1] = *reinterpret_cast<const uint32_t*>(ap + 8 * HSTR);
        af[2] = *reinterpret_cast<const uint32_t*>(ap + 8);
        af[3] = *reinterpret_cast<const uint32_t*>(ap + 8 * HSTR + 8);
        #pragma unroll
        for (int ni = 0; ni < 15; ni++) {
            uint32_t bf[2];
            const __half* bp = Ws + (wnl + ni * 8 + r) * HSTR + k0 + 2 * cc;
            bf[0] = *reinterpret_cast<const uint32_t*>(bp);
            bf[1] = *reinterpret_cast<const uint32_t*>(bp + 8);
            mma_f16(acc[ni], af, bf);
        }
    }

    #pragma unroll
    for (int ni = 0; ni < 15; ni++) {
        int l = wnl + ni * 8 + 2 * cc;
        float bv0 = __ldg(&b2[l]), bv1 = __ldg(&b2[l + 1]);
        size_t row0 = (size_t)b * Nn + n0 + wm + r;
        float2 v0 = make_float2(acc[ni][0] + bv0, acc[ni][1] + bv1);
        float2 v1 = make_float2(acc[ni][2] + bv0, acc[ni][3] + bv1);
        *reinterpret_cast<float2*>(&out[row0 * Ll + l])       = v0;
        *reinterpret_cast<float2*>(&out[(row0 + 8) * Ll + l]) = v1;
    }
}

// ===========================================================================
extern "C" void kernel_launch(void* const* d_in, const int* in_sizes, int n_in,
                              void* d_out, int out_size) {
    const float* x  = (const float*)d_in[0];
    const float* a  = (const float*)d_in[1];
    const float* W1 = (const float*)d_in[2];
    const float* b1 = (const float*)d_in[3];
    const float* W2 = (const float*)d_in[4];
    const float* b2 = (const float*)d_in[5];
    float* out = (float*)d_out;

    cudaFuncSetAttribute(k01, cudaFuncAttributeMaxDynamicSharedMemorySize,
                         K01_SMEM);
    k01<<<9217, 256, K01_SMEM>>>(a, W2, x, W1);

    cudaFuncSetAttribute(k2_tc, cudaFuncAttributeMaxDynamicSharedMemorySize,
                         K2_SMEM);
    dim3 g2(Nn / K2_BM, NC / K2_BN, KSPLIT);
    k2_tc<<<g2, 512, K2_SMEM>>>();

    dim3 g3(Nn / 32, Bb);
    k3_out<<<g3, 128>>>(b1, b2, out);
}